// round 3
// baseline (speedup 1.0000x reference)
#include <cuda_runtime.h>
#include <math.h>

#define KC 8192   // codebook size
#define DD 128    // embed dim
#define NR 8192   // number of z rows
#define TM 64     // z rows per argmin block
#define TN 128    // codes per k-tile
#define NTILES (KC / TN)

typedef unsigned long long ull;

__device__ float g_qc[KC * DD];
__device__ float g_cnorm[KC];
__device__ float g_counts[KC];
__device__ float g_commit;

// ---- packed f32x2 FFMA (Blackwell) ----
__device__ __forceinline__ ull ffma2(ull a, ull b, ull c) {
    ull d;
    asm("fma.rn.f32x2 %0, %1, %2, %3;" : "=l"(d) : "l"(a), "l"(b), "l"(c));
    return d;
}
__device__ __forceinline__ float2 unpack2(ull v) {
    float2 r;
    asm("mov.b64 {%0, %1}, %2;" : "=f"(r.x), "=f"(r.y) : "l"(v));
    return r;
}
__device__ __forceinline__ void cp16(void* dst, const void* src) {
    unsigned d = (unsigned)__cvta_generic_to_shared(dst);
    asm volatile("cp.async.cg.shared.global [%0], [%1], 16;" :: "r"(d), "l"(src));
}
__device__ __forceinline__ void cp_commit() {
    asm volatile("cp.async.commit_group;");
}
__device__ __forceinline__ void cp_wait0() {
    asm volatile("cp.async.wait_group 0;");
}

extern __shared__ float smem_dyn[];

// ---------------------------------------------------------------------------
// Kernel 1: qc = emb @ pw^T + pb ; cnorm ; init counts/commit.
// 128 blocks x 64 codes, 256 threads, 4x8 micro-tile.
// ---------------------------------------------------------------------------
__global__ __launch_bounds__(256) void k_proj(const float* __restrict__ emb,
                                              const float* __restrict__ pw,
                                              const float* __restrict__ pb) {
    float* pwT = smem_dyn;            // [k*128 + n]   16384 fl
    float* ebT = smem_dyn + 16384;    // [k*64 + c]     8192 fl
    float* cn_s = ebT + 8192;         // [64]

    const int tid = threadIdx.x;
    const int c0 = blockIdx.x * 64;

    if (tid < 64) { g_counts[c0 + tid] = 0.f; cn_s[tid] = 0.f; }
    if (blockIdx.x == 0 && tid == 0) g_commit = 0.f;

    // pw transposed: pwT[k][n] = pw[n][k]
    {
        int n = tid & 127, h = tid >> 7;
        const float4* pr = (const float4*)(pw + (size_t)n * DD) + h * 16;
#pragma unroll
        for (int i = 0; i < 16; i++) {
            float4 v = pr[i];
            int k = (h * 16 + i) * 4;
            pwT[(k + 0) * 128 + n] = v.x; pwT[(k + 1) * 128 + n] = v.y;
            pwT[(k + 2) * 128 + n] = v.z; pwT[(k + 3) * 128 + n] = v.w;
        }
    }
    // emb rows transposed: ebT[k][c]
    {
        int c = tid & 63, h = tid >> 6;
        const float4* er = (const float4*)(emb + (size_t)(c0 + c) * DD) + h * 8;
#pragma unroll
        for (int i = 0; i < 8; i++) {
            float4 v = er[i];
            int k = (h * 8 + i) * 4;
            ebT[(k + 0) * 64 + c] = v.x; ebT[(k + 1) * 64 + c] = v.y;
            ebT[(k + 2) * 64 + c] = v.z; ebT[(k + 3) * 64 + c] = v.w;
        }
    }
    __syncthreads();

    const int rg = tid >> 4;  // 0..15 -> codes rg*4..rg*4+3
    const int tc = tid & 15;  // 0..15 -> dims tc*4+j, 64+tc*4+j

    float acc[4][8];
#pragma unroll
    for (int i = 0; i < 4; i++)
#pragma unroll
        for (int j = 0; j < 8; j++) acc[i][j] = 0.f;

#pragma unroll 4
    for (int k = 0; k < DD; k++) {
        float4 a = *(const float4*)(ebT + k * 64 + rg * 4);
        float4 b0 = *(const float4*)(pwT + k * 128 + tc * 4);
        float4 b1 = *(const float4*)(pwT + k * 128 + 64 + tc * 4);
        float av[4] = {a.x, a.y, a.z, a.w};
        float bv[8] = {b0.x, b0.y, b0.z, b0.w, b1.x, b1.y, b1.z, b1.w};
#pragma unroll
        for (int i = 0; i < 4; i++)
#pragma unroll
            for (int j = 0; j < 8; j++) acc[i][j] += av[i] * bv[j];
    }

    float pbv[8];
#pragma unroll
    for (int j = 0; j < 8; j++)
        pbv[j] = pb[(j < 4) ? (tc * 4 + j) : (64 + tc * 4 + (j - 4))];

#pragma unroll
    for (int i = 0; i < 4; i++) {
        int code = rg * 4 + i;
        float s = 0.f;
        float4 o0, o1;
        float v;
        v = acc[i][0] + pbv[0]; o0.x = v; s += v * v;
        v = acc[i][1] + pbv[1]; o0.y = v; s += v * v;
        v = acc[i][2] + pbv[2]; o0.z = v; s += v * v;
        v = acc[i][3] + pbv[3]; o0.w = v; s += v * v;
        v = acc[i][4] + pbv[4]; o1.x = v; s += v * v;
        v = acc[i][5] + pbv[5]; o1.y = v; s += v * v;
        v = acc[i][6] + pbv[6]; o1.z = v; s += v * v;
        v = acc[i][7] + pbv[7]; o1.w = v; s += v * v;
        float* qr = g_qc + (size_t)(c0 + code) * DD;
        *(float4*)(qr + tc * 4) = o0;
        *(float4*)(qr + 64 + tc * 4) = o1;
        atomicAdd(&cn_s[code], s);
    }
    __syncthreads();
    if (tid < 64) g_cnorm[c0 + tid] = cn_s[tid];
}

// ---------------------------------------------------------------------------
// Kernel 2: fused distance + argmin + gather + counts + commit.
// FFMA2 packed along D; blocked smem [d4][col][4]; cp.async double buffer.
// 128 blocks x 64 rows; 256 threads (8 warps x 8 rows); thread = 8 rows x 4 cols.
// dyn smem: zs 32KB + cs0 64KB + cs1 64KB = 160KB
// ---------------------------------------------------------------------------
__device__ __forceinline__ void load_tile_async(float* dst, int kt, int tid) {
    int c = tid & 127, h = tid >> 7;
    const float4* gsrc = (const float4*)(g_qc + (size_t)(kt + c) * DD) + h * 16;
#pragma unroll
    for (int i = 0; i < 16; i++) {
        int d4 = h * 16 + i;
        cp16(dst + d4 * (TN * 4) + c * 4, gsrc + i);
    }
}

__global__ __launch_bounds__(256, 1) void k_argmin(const float* __restrict__ z,
                                                   float* __restrict__ out) {
    float* zs = smem_dyn;                 // [d4][row][4] : 8192 fl
    float* cs0 = smem_dyn + 8192;         // [d4][col][4] : 16384 fl
    float* cs1 = cs0 + 16384;
    __shared__ ull bestkey[TM];
    __shared__ float credu[8];

    const int tid = threadIdx.x;
    const int wid = tid >> 5;
    const int lane = tid & 31;
    const int n0 = blockIdx.x * TM;

    // load z tile into blocked layout (STS.128, coalesced)
    {
        int r = tid & 63, h = tid >> 6;
        const float4* zr = (const float4*)(z + (size_t)(n0 + r) * DD) + h * 8;
#pragma unroll
        for (int i = 0; i < 8; i++) {
            int d4 = h * 8 + i;
            *(float4*)(zs + d4 * (TM * 4) + r * 4) = zr[i];
        }
    }
    // prefetch first code tile
    load_tile_async(cs0, 0, tid);
    cp_commit();
    __syncthreads();  // zs visible

    // per-warp row norms: lane i<8 computes row wid*8+i sequentially (ref order)
    float mynorm = 0.f;
    if (lane < 8) {
        int r = wid * 8 + lane;
#pragma unroll 8
        for (int d = 0; d < DD; d++)
            { float v = zs[(d >> 2) * (TM * 4) + r * 4 + (d & 3)]; mynorm += v * v; }
    }
    float zn[8];
#pragma unroll
    for (int i = 0; i < 8; i++) zn[i] = __shfl_sync(0xffffffffu, mynorm, i);

    float bestv[8];
    int bestidx[8];
#pragma unroll
    for (int i = 0; i < 8; i++) { bestv[i] = 3.4e38f; bestidx[i] = 0; }

    const float* zw = zs + (wid * 8) * 4;  // this warp's 8 rows
    for (int t = 0; t < NTILES; t++) {
        cp_wait0();
        __syncthreads();  // current tile ready; prior tile fully consumed
        float* cur = (t & 1) ? cs1 : cs0;
        if (t + 1 < NTILES) { load_tile_async((t & 1) ? cs0 : cs1, (t + 1) * TN, tid); cp_commit(); }

        ull acc[8][4];
#pragma unroll
        for (int i = 0; i < 8; i++)
#pragma unroll
            for (int j = 0; j < 4; j++) acc[i][j] = 0ULL;

        const float* cbt = cur + lane * 4;
#pragma unroll 8
        for (int d4 = 0; d4 < DD / 4; d4++) {
            ulonglong2 bb[4];
#pragma unroll
            for (int j = 0; j < 4; j++)
                bb[j] = *(const ulonglong2*)(cbt + d4 * (TN * 4) + j * 128);
#pragma unroll
            for (int i = 0; i < 8; i++) {
                ulonglong2 aa = *(const ulonglong2*)(zw + d4 * (TM * 4) + i * 4);
#pragma unroll
                for (int j = 0; j < 4; j++) {
                    acc[i][j] = ffma2(aa.x, bb[j].x, acc[i][j]);
                    acc[i][j] = ffma2(aa.y, bb[j].y, acc[i][j]);
                }
            }
        }

        // epilogue: d = (||z||^2 + ||c||^2) - 2*dot
        int kb = t * TN;
#pragma unroll
        for (int j = 0; j < 4; j++) {
            int code = kb + lane + 32 * j;
            float cn = __ldg(&g_cnorm[code]);
#pragma unroll
            for (int i = 0; i < 8; i++) {
                float2 dp = unpack2(acc[i][j]);
                float dot = dp.x + dp.y;
                float sc = (zn[i] + cn) - 2.0f * dot;
                if (sc < bestv[i]) { bestv[i] = sc; bestidx[i] = code; }
            }
        }
    }

    // intra-warp argmin reduce per row: packed (dist||idx) u64 min keeps
    // smallest distance, then smallest index (matches jnp.argmin)
#pragma unroll
    for (int i = 0; i < 8; i++) {
        unsigned ub = __float_as_uint(bestv[i]);
        ub = (ub & 0x80000000u) ? ~ub : (ub | 0x80000000u);
        ull key = ((ull)ub << 32) | (unsigned)bestidx[i];
#pragma unroll
        for (int o = 16; o; o >>= 1) {
            ull other = __shfl_xor_sync(0xffffffffu, key, o);
            if (other < key) key = other;
        }
        if (lane == 0) bestkey[wid * 8 + i] = key;
    }
    __syncthreads();

    if (tid < TM) {
        unsigned idxk = (unsigned)(bestkey[tid] & 0xffffffffu);
        atomicAdd(&g_counts[idxk], 1.0f);
    }

    // gather z_q = z + (qc[idx]-z); accumulate commit partial
    float csum = 0.f;
    {
        int r = tid >> 2, part = tid & 3;
        unsigned idxk = (unsigned)(bestkey[r] & 0xffffffffu);
        const float4* qv = (const float4*)(g_qc + (size_t)idxk * DD) + part * 8;
        const float4* zv = (const float4*)(z + (size_t)(n0 + r) * DD) + part * 8;
        float4* ov = (float4*)(out + (size_t)(n0 + r) * DD) + part * 8;
#pragma unroll
        for (int i = 0; i < 8; i++) {
            float4 q = qv[i], zz = zv[i], o;
            float dx = q.x - zz.x, dy = q.y - zz.y, dz2 = q.z - zz.z, dw = q.w - zz.w;
            o.x = zz.x + dx; o.y = zz.y + dy; o.z = zz.z + dz2; o.w = zz.w + dw;
            ov[i] = o;
            csum += dx * dx; csum += dy * dy; csum += dz2 * dz2; csum += dw * dw;
        }
    }
#pragma unroll
    for (int o = 16; o; o >>= 1) csum += __shfl_xor_sync(0xffffffffu, csum, o);
    if ((tid & 31) == 0) credu[tid >> 5] = csum;
    __syncthreads();
    if (tid == 0) {
        float tt = 0.f;
#pragma unroll
        for (int i = 0; i < 8; i++) tt += credu[i];
        atomicAdd(&g_commit, tt);
    }
}

// ---------------------------------------------------------------------------
// Kernel 3: finalize scalars
// ---------------------------------------------------------------------------
__global__ __launch_bounds__(256) void k_final(const float* __restrict__ ema,
                                               float* __restrict__ out,
                                               int out_size) {
    __shared__ float r1[8], r2[8];
    int tid = threadIdx.x;
    const float omd = 1.0f - 0.99f;
    float s1 = 0.f, s2 = 0.f;
    for (int k = tid; k < KC; k += 256) {
        float em = g_counts[k] * (1.0f / NR);
        s1 += em * logf(em + 1e-10f);
        float nu = ema[k] * 0.99f + em * omd;
        s2 += nu * logf(nu + 1e-10f);
    }
#pragma unroll
    for (int o = 16; o; o >>= 1) {
        s1 += __shfl_xor_sync(0xffffffffu, s1, o);
        s2 += __shfl_xor_sync(0xffffffffu, s2, o);
    }
    if ((tid & 31) == 0) { r1[tid >> 5] = s1; r2[tid >> 5] = s2; }
    __syncthreads();
    if (tid == 0) {
        float S1 = 0.f, S2 = 0.f;
#pragma unroll
        for (int i = 0; i < 8; i++) { S1 += r1[i]; S2 += r2[i]; }
        out[out_size - 3] = 1.25f * g_commit * (1.0f / ((float)NR * (float)DD));
        out[out_size - 2] = expf(-S1);
        out[out_size - 1] = -S2;
    }
}

// ---------------------------------------------------------------------------
extern "C" void kernel_launch(void* const* d_in, const int* in_sizes, int n_in,
                              void* d_out, int out_size) {
    const float* z   = (const float*)d_in[0];
    const float* emb = (const float*)d_in[1];
    const float* pw  = (const float*)d_in[2];
    const float* pb  = (const float*)d_in[3];
    const float* ema = (const float*)d_in[4];
    float* out = (float*)d_out;

    const int smem_proj = (16384 + 8192 + 64) * 4;            // 98560
    const int smem_arg  = (8192 + 2 * 16384) * 4;             // 163840
    cudaFuncSetAttribute(k_proj, cudaFuncAttributeMaxDynamicSharedMemorySize,
                         smem_proj);
    cudaFuncSetAttribute(k_argmin, cudaFuncAttributeMaxDynamicSharedMemorySize,
                         smem_arg);

    k_proj<<<KC / 64, 256, smem_proj>>>(emb, pw, pb);
    k_argmin<<<NR / TM, 256, smem_arg>>>(z, out);
    k_final<<<1, 256>>>(ema, out, out_size);
}